// round 1
// baseline (speedup 1.0000x reference)
#include <cuda_runtime.h>
#include <math.h>

// Problem constants
#define NP     2048     // particles
#define NR     128      // rays
#define NS     256      // ray steps
#define MAPW   1024
#define MAPH   1024
#define ND     256      // sensor table dim
#define OCC_THRESH 0.97f

// Scratch (no cudaMalloc allowed)
__device__ float g_pred[NP * 3];    // predicted particles
__device__ float g_logl[NP];        // per-particle log likelihood
__device__ float g_logits[NP];      // log_weights + log_l

// ---------------------------------------------------------------------------
// Kernel A: one block per particle, one thread per ray.
// Motion update + ray march (early exit) + sensor table gather + block reduce.
// ---------------------------------------------------------------------------
__global__ __launch_bounds__(128) void kernA(
    const float* __restrict__ particles,
    const float* __restrict__ log_weights,
    const float* __restrict__ obs_angles,
    const float* __restrict__ obs_dists,
    const float* __restrict__ map_grid,
    const float* __restrict__ sensor_table,
    const float* __restrict__ twist,
    const float* __restrict__ motion_noise)
{
    const int p = blockIdx.x;
    const int r = threadIdx.x;

    // Motion update: p = particles + twist + motion_noise * SIGMA_MOTION
    // SIGMA_MOTION = (0.5, 0.5, 0.02). Keep mul and add separate (no FMA) to
    // match XLA's elementwise mul-then-add.
    float x  = __fadd_rn(__fadd_rn(particles[p*3+0], twist[0]),
                         __fmul_rn(motion_noise[p*3+0], 0.5f));
    float y  = __fadd_rn(__fadd_rn(particles[p*3+1], twist[1]),
                         __fmul_rn(motion_noise[p*3+1], 0.5f));
    float th = __fadd_rn(__fadd_rn(particles[p*3+2], twist[2]),
                         __fmul_rn(motion_noise[p*3+2], 0.02f));

    if (r < 3) {
        g_pred[p*3 + r] = (r == 0) ? x : ((r == 1) ? y : th);
    }

    // Ray march
    const float ang = __fadd_rn(th, obs_angles[r]);
    const float c = cosf(ang);
    const float s = sinf(ang);

    int ebin = 255;   // no-hit: dist = 256 -> clip(int(256),0,255) = 255
    bool done = false;
    for (int base = 0; base < NS; base += 8) {
        float v[8];
        #pragma unroll
        for (int j = 0; j < 8; j++) {
            float tf = (float)(base + j + 1);  // t = (k+1)*STEP, STEP=1
            float px = __fadd_rn(x, __fmul_rn(tf, c));
            float py = __fadd_rn(y, __fmul_rn(tf, s));
            int ix = __float2int_rz(px);
            int iy = __float2int_rz(py);
            ix = min(max(ix, 0), MAPW - 1);
            iy = min(max(iy, 0), MAPH - 1);
            v[j] = __ldg(&map_grid[iy * MAPW + ix]);
        }
        #pragma unroll
        for (int j = 0; j < 8; j++) {
            if (v[j] > OCC_THRESH) {
                int t = base + j + 1;
                ebin = min(t, 255);
                done = true;
                break;
            }
        }
        if (done) break;
    }

    // o_bin: bin_w = MAX_DIST/D = 1.0 exactly, so o_bin = clip(int(obs_dist))
    int ob = __float2int_rz(obs_dists[r]);
    ob = min(max(ob, 0), ND - 1);

    float val = __ldg(&sensor_table[ebin * ND + ob]);

    // Deterministic tree reduction over 128 threads (4 warps)
    __shared__ float s_part[4];
    #pragma unroll
    for (int o = 16; o > 0; o >>= 1)
        val += __shfl_down_sync(0xffffffffu, val, o);
    if ((r & 31) == 0) s_part[r >> 5] = val;
    __syncthreads();
    if (r == 0) {
        float ll = ((s_part[0] + s_part[1]) + s_part[2]) + s_part[3];
        g_logl[p] = ll;
        g_logits[p] = __fadd_rn(log_weights[p], __fmul_rn(1.0f, ll));
    }
}

// ---------------------------------------------------------------------------
// Kernel B: single block, 1024 threads. Softmaxes, estimates, cumsum,
// systematic resampling, output assembly.
// ---------------------------------------------------------------------------
__device__ __forceinline__ float blockReduceSum(float v, float* s_red) {
    #pragma unroll
    for (int o = 16; o > 0; o >>= 1)
        v += __shfl_down_sync(0xffffffffu, v, o);
    int w = threadIdx.x >> 5, l = threadIdx.x & 31;
    if (l == 0) s_red[w] = v;
    __syncthreads();
    if (w == 0) {
        v = s_red[l];
        #pragma unroll
        for (int o = 16; o > 0; o >>= 1)
            v += __shfl_down_sync(0xffffffffu, v, o);
        if (l == 0) s_red[0] = v;
    }
    __syncthreads();
    float res = s_red[0];
    __syncthreads();
    return res;
}

__device__ __forceinline__ float blockReduceMax(float v, float* s_red) {
    #pragma unroll
    for (int o = 16; o > 0; o >>= 1)
        v = fmaxf(v, __shfl_down_sync(0xffffffffu, v, o));
    int w = threadIdx.x >> 5, l = threadIdx.x & 31;
    if (l == 0) s_red[w] = v;
    __syncthreads();
    if (w == 0) {
        v = s_red[l];
        #pragma unroll
        for (int o = 16; o > 0; o >>= 1)
            v = fmaxf(v, __shfl_down_sync(0xffffffffu, v, o));
        if (l == 0) s_red[0] = v;
    }
    __syncthreads();
    float res = s_red[0];
    __syncthreads();
    return res;
}

__global__ __launch_bounds__(1024) void kernB(
    const float* __restrict__ noise_after,
    const float* __restrict__ resample_u,
    float* __restrict__ out)
{
    __shared__ float s_cum[NP];
    __shared__ float s_red[32];

    const int tid = threadIdx.x;
    const int i0 = tid, i1 = tid + 1024;

    // --- max of logits ---
    float l0 = g_logits[i0];
    float l1 = g_logits[i1];
    float mx = blockReduceMax(fmaxf(l0, l1), s_red);
    // max of (logits*10): rounding is monotone, so max(round(10*l)) = round(10*max)
    float mx10 = __fmul_rn(mx, 10.0f);

    // --- exp terms + fused weighted partial sums ---
    float S10 = 0.f, Sx = 0.f, Sy = 0.f, Ssin = 0.f, Scos = 0.f;
    float S1 = 0.f, Sconf = 0.f;
    #pragma unroll
    for (int k = 0; k < 2; k++) {
        int i = (k == 0) ? i0 : i1;
        float l = (k == 0) ? l0 : l1;
        // match jax: x = logits*10 (rounded), then x - max(x), then exp
        float e10 = expf(__fsub_rn(__fmul_rn(l, 10.0f), mx10));
        float e1  = expf(__fsub_rn(l, mx));
        float px = g_pred[i*3+0];
        float py = g_pred[i*3+1];
        float pth = g_pred[i*3+2];
        S10  += e10;
        Sx   += e10 * px;
        Sy   += e10 * py;
        Ssin += e10 * sinf(pth);
        Scos += e10 * cosf(pth);
        S1   += e1;
        Sconf += e1 * g_logl[i];
        s_cum[i] = e1;
    }
    S10   = blockReduceSum(S10, s_red);
    Sx    = blockReduceSum(Sx, s_red);
    Sy    = blockReduceSum(Sy, s_red);
    Ssin  = blockReduceSum(Ssin, s_red);
    Scos  = blockReduceSum(Scos, s_red);
    S1    = blockReduceSum(S1, s_red);
    Sconf = blockReduceSum(Sconf, s_red);

    // --- normalize weights (w = e1 / S1), then inclusive scan (Kogge-Stone) ---
    s_cum[i0] = s_cum[i0] / S1;
    s_cum[i1] = s_cum[i1] / S1;
    __syncthreads();

    for (int stride = 1; stride < NP; stride <<= 1) {
        float a0 = (i0 >= stride) ? s_cum[i0 - stride] : 0.f;
        float a1 = (i1 >= stride) ? s_cum[i1 - stride] : 0.f;
        __syncthreads();
        if (i0 >= stride) s_cum[i0] += a0;
        if (i1 >= stride) s_cum[i1] += a1;
        __syncthreads();
    }

    // --- systematic resampling: idx = searchsorted(cum, (i+u)/P), side=left ---
    const float u = resample_u[0];
    #pragma unroll
    for (int k = 0; k < 2; k++) {
        int i = (k == 0) ? i0 : i1;
        float pos = __fdiv_rn(__fadd_rn((float)i, u), (float)NP);
        int lo = 0, hi = NP;
        while (lo < hi) {
            int mid = (lo + hi) >> 1;
            if (s_cum[mid] < pos) lo = mid + 1;
            else hi = mid;
        }
        int idx = min(lo, NP - 1);
        // new_p = p[idx] + noise_after * SIGMA_NOISE, SIGMA_NOISE=(0.2,0.2,0.01)
        out[3 + i*3 + 0] = __fadd_rn(g_pred[idx*3+0], __fmul_rn(noise_after[i*3+0], 0.2f));
        out[3 + i*3 + 1] = __fadd_rn(g_pred[idx*3+1], __fmul_rn(noise_after[i*3+1], 0.2f));
        out[3 + i*3 + 2] = __fadd_rn(g_pred[idx*3+2], __fmul_rn(noise_after[i*3+2], 0.01f));
    }

    if (tid == 0) {
        out[0] = Sx / S10;
        out[1] = Sy / S10;
        out[2] = atan2f(Ssin / S10, Scos / S10);
        out[3 + NP * 3] = Sconf / S1;   // confidence, last element
    }
}

// ---------------------------------------------------------------------------
// Launch
// ---------------------------------------------------------------------------
extern "C" void kernel_launch(void* const* d_in, const int* in_sizes, int n_in,
                              void* d_out, int out_size)
{
    const float* particles    = (const float*)d_in[0];
    const float* log_weights  = (const float*)d_in[1];
    const float* obs_angles   = (const float*)d_in[2];
    const float* obs_dists    = (const float*)d_in[3];
    const float* map_grid     = (const float*)d_in[4];
    const float* sensor_table = (const float*)d_in[5];
    const float* twist        = (const float*)d_in[6];
    const float* motion_noise = (const float*)d_in[7];
    const float* resample_u   = (const float*)d_in[8];
    const float* noise_after  = (const float*)d_in[9];
    float* out = (float*)d_out;

    kernA<<<NP, 128>>>(particles, log_weights, obs_angles, obs_dists,
                       map_grid, sensor_table, twist, motion_noise);
    kernB<<<1, 1024>>>(noise_after, resample_u, out);
}